// round 1
// baseline (speedup 1.0000x reference)
#include <cuda_runtime.h>
#include <cstdint>

// TransducerJoint:
//   enc  = encoder_outputs @ W_enc^T + b_enc          (B*T=1600, H=512)
//   pred = predictor_outputs @ W_pred^T + b_pred      (B*U=800,  H=512)
//   out[b,t,u,:] = (relu(enc[b,t,:]+pred[b,u,:]) @ W_out^T + b_out) * 0.1
//
// Strategy: two small projection GEMMs into __device__ scratch, then one big
// fused GEMM (M=160000, N=1024, K=512) whose A-tile loader computes
// relu(enc+pred) on the fly (joint tensor never materialized).

#define B_ 8
#define T_ 200
#define U_ 100
#define H_ 512
#define V_ 1024

__device__ float g_enc[B_ * T_ * H_];   // 3.2 MB
__device__ float g_pred[B_ * U_ * H_];  // 1.6 MB

// ---------------------------------------------------------------------------
// proj: out[m,n] = sum_k A[m,k] * W[n,k] + bias[n]
// BM=BN=64, BK=16, 256 threads, 4x4 micro-tile. N multiple of 64, K mult of 16.
// ---------------------------------------------------------------------------
__global__ __launch_bounds__(256) void proj_kernel(
    const float* __restrict__ A, const float* __restrict__ W,
    const float* __restrict__ bias, float* __restrict__ out,
    int M, int N, int K)
{
    __shared__ float As[16][68];
    __shared__ float Ws[16][68];
    const int tid = threadIdx.x;
    const int tx = tid & 15, ty = tid >> 4;
    const int m0 = blockIdx.y * 64, n0 = blockIdx.x * 64;
    const int lm = tid >> 2;           // 0..63
    const int lk = (tid & 3) << 2;     // 0,4,8,12
    const int arow = m0 + lm;
    const float* Ap = A + (size_t)arow * K;
    const float* Wp = W + (size_t)(n0 + lm) * K;
    float acc[4][4] = {};

    for (int k0 = 0; k0 < K; k0 += 16) {
        float4 av = make_float4(0.f, 0.f, 0.f, 0.f);
        if (arow < M) av = *(const float4*)(Ap + k0 + lk);
        float4 wv = *(const float4*)(Wp + k0 + lk);
        As[lk+0][lm] = av.x; As[lk+1][lm] = av.y;
        As[lk+2][lm] = av.z; As[lk+3][lm] = av.w;
        Ws[lk+0][lm] = wv.x; Ws[lk+1][lm] = wv.y;
        Ws[lk+2][lm] = wv.z; Ws[lk+3][lm] = wv.w;
        __syncthreads();
        #pragma unroll
        for (int kk = 0; kk < 16; kk++) {
            float a[4], w[4];
            *(float4*)a = *(const float4*)&As[kk][ty << 2];
            *(float4*)w = *(const float4*)&Ws[kk][tx << 2];
            #pragma unroll
            for (int i = 0; i < 4; i++)
                #pragma unroll
                for (int j = 0; j < 4; j++)
                    acc[i][j] = fmaf(a[i], w[j], acc[i][j]);
        }
        __syncthreads();
    }

    float4 bv = *(const float4*)(bias + n0 + (tx << 2));
    #pragma unroll
    for (int i = 0; i < 4; i++) {
        int row = m0 + (ty << 2) + i;
        if (row < M) {
            float4 v;
            v.x = acc[i][0] + bv.x; v.y = acc[i][1] + bv.y;
            v.z = acc[i][2] + bv.z; v.w = acc[i][3] + bv.w;
            *(float4*)(out + (size_t)row * N + n0 + (tx << 2)) = v;
        }
    }
}

// ---------------------------------------------------------------------------
// Fused joint GEMM: out[r, n] = (relu(enc[bt]+pred[bu]) . Wout[n,:]) + bout[n],
// all scaled by 0.1.  M=160000, N=1024, K=512 — all tiles exact, no guards.
// BM=BN=128, BK=8, 256 threads, 8x8 micro-tile (2x2 of 4x4).
// ---------------------------------------------------------------------------
__global__ __launch_bounds__(256) void joint_kernel(
    const float* __restrict__ Wout, const float* __restrict__ bout,
    float* __restrict__ out)
{
    __shared__ float As[8][132];
    __shared__ float Bs[8][132];
    const int tid = threadIdx.x;
    const int tx = tid & 15, ty = tid >> 4;
    const int m0 = blockIdx.y * 128;
    const int n0 = blockIdx.x * 128;

    // A loader: thread -> (row lm, k-quad lk)
    const int lm = tid >> 1;          // 0..127
    const int lk = (tid & 1) << 2;    // 0 or 4
    const int row = m0 + lm;          // flattened (b,t,u) row
    const int bt = row / U_;          // 0..1599
    const int u  = row - bt * U_;
    const int bb = bt / T_;
    const float* encp  = g_enc  + (size_t)bt * H_;
    const float* predp = g_pred + (size_t)(bb * U_ + u) * H_;
    const float* wp    = Wout   + (size_t)(n0 + lm) * H_;

    float acc[8][8] = {};

    for (int k0 = 0; k0 < H_; k0 += 8) {
        float4 e = *(const float4*)(encp  + k0 + lk);
        float4 p = *(const float4*)(predp + k0 + lk);
        float4 w = *(const float4*)(wp    + k0 + lk);
        As[lk+0][lm] = fmaxf(e.x + p.x, 0.f);
        As[lk+1][lm] = fmaxf(e.y + p.y, 0.f);
        As[lk+2][lm] = fmaxf(e.z + p.z, 0.f);
        As[lk+3][lm] = fmaxf(e.w + p.w, 0.f);
        Bs[lk+0][lm] = w.x; Bs[lk+1][lm] = w.y;
        Bs[lk+2][lm] = w.z; Bs[lk+3][lm] = w.w;
        __syncthreads();
        #pragma unroll
        for (int kk = 0; kk < 8; kk++) {
            float a[8], bf[8];
            *(float4*)(a)    = *(const float4*)&As[kk][ty << 2];
            *(float4*)(a+4)  = *(const float4*)&As[kk][64 + (ty << 2)];
            *(float4*)(bf)   = *(const float4*)&Bs[kk][tx << 2];
            *(float4*)(bf+4) = *(const float4*)&Bs[kk][64 + (tx << 2)];
            #pragma unroll
            for (int i = 0; i < 8; i++)
                #pragma unroll
                for (int j = 0; j < 8; j++)
                    acc[i][j] = fmaf(a[i], bf[j], acc[i][j]);
        }
        __syncthreads();
    }

    float4 bias0 = *(const float4*)(bout + n0 + (tx << 2));
    float4 bias1 = *(const float4*)(bout + n0 + 64 + (tx << 2));
    #pragma unroll
    for (int ih = 0; ih < 2; ih++) {
        #pragma unroll
        for (int i = 0; i < 4; i++) {
            const int ai = ih * 4 + i;
            const int r = m0 + ih * 64 + (ty << 2) + i;
            const size_t base = (size_t)r * V_ + n0;
            float4 v0, v1;
            v0.x = (acc[ai][0] + bias0.x) * 0.1f;
            v0.y = (acc[ai][1] + bias0.y) * 0.1f;
            v0.z = (acc[ai][2] + bias0.z) * 0.1f;
            v0.w = (acc[ai][3] + bias0.w) * 0.1f;
            v1.x = (acc[ai][4] + bias1.x) * 0.1f;
            v1.y = (acc[ai][5] + bias1.y) * 0.1f;
            v1.z = (acc[ai][6] + bias1.z) * 0.1f;
            v1.w = (acc[ai][7] + bias1.w) * 0.1f;
            *(float4*)(out + base + (tx << 2)) = v0;
            *(float4*)(out + base + 64 + (tx << 2)) = v1;
        }
    }
}

extern "C" void kernel_launch(void* const* d_in, const int* in_sizes, int n_in,
                              void* d_out, int out_size)
{
    const float* enc_in  = (const float*)d_in[0];  // (B,T,E)
    const float* pred_in = (const float*)d_in[1];  // (B,U,P)
    const float* W_enc   = (const float*)d_in[2];  // (H,E)
    const float* b_enc   = (const float*)d_in[3];  // (H)
    const float* W_pred  = (const float*)d_in[4];  // (H,P)
    const float* b_pred  = (const float*)d_in[5];  // (H)
    const float* W_out   = (const float*)d_in[6];  // (V,H)
    const float* b_out   = (const float*)d_in[7];  // (V)
    float* out = (float*)d_out;

    float *genc = nullptr, *gpred = nullptr;
    cudaGetSymbolAddress((void**)&genc, g_enc);
    cudaGetSymbolAddress((void**)&gpred, g_pred);

    // enc: M=1600, N=512, K=512
    proj_kernel<<<dim3(512 / 64, (1600 + 63) / 64), 256>>>(
        enc_in, W_enc, b_enc, genc, 1600, 512, 512);
    // pred: M=800, N=512, K=640
    proj_kernel<<<dim3(512 / 64, (800 + 63) / 64), 256>>>(
        pred_in, W_pred, b_pred, gpred, 800, 512, 640);
    // joint: M=160000, N=1024, K=512
    joint_kernel<<<dim3(1024 / 128, 160000 / 128), 256>>>(W_out, b_out, out);
}

// round 3
// speedup vs baseline: 3.7461x; 3.7461x over previous
#include <cuda_runtime.h>
#include <cuda_fp16.h>
#include <cstdint>

#define B_ 8
#define T_ 200
#define U_ 100
#define H_ 512
#define V_ 1024

__device__ float  g_enc [B_ * T_ * H_];   // 3.2 MB fp32 (B*T=1600, H)
__device__ float  g_pred[B_ * U_ * H_];   // 1.6 MB fp32 (B*U=800,  H)
__device__ __half g_wout[V_ * H_];        // 1.0 MB fp16 (V=1024, H)

// ───────────── helpers ─────────────
__device__ __forceinline__ uint32_t smem_u32(const void* p) {
    uint32_t a;
    asm("{ .reg .u64 t; cvta.to.shared.u64 t, %1; cvt.u32.u64 %0, t; }" : "=r"(a) : "l"(p));
    return a;
}
__device__ __forceinline__ uint32_t pack_h2(float x, float y) {
    __half2 h = __floats2half2_rn(x, y);
    return *reinterpret_cast<uint32_t*>(&h);
}
#define CP_ASYNC16(dst, src) \
    asm volatile("cp.async.cg.shared.global [%0], [%1], 16;" :: "r"(dst), "l"(src) : "memory")
#define CP_COMMIT() asm volatile("cp.async.commit_group;" ::: "memory")
#define CP_WAIT0()  asm volatile("cp.async.wait_group 0;" ::: "memory")

#define LDMATRIX_X4(r0, r1, r2, r3, addr) \
    asm volatile("ldmatrix.sync.aligned.m8n8.x4.shared.b16 {%0,%1,%2,%3}, [%4];" \
                 : "=r"(r0), "=r"(r1), "=r"(r2), "=r"(r3) : "r"(addr))

#define MMA16816(c, a, b0, b1) \
    asm volatile("mma.sync.aligned.m16n8k16.row.col.f32.f16.f16.f32 " \
                 "{%0,%1,%2,%3}, {%4,%5,%6,%7}, {%8,%9}, {%0,%1,%2,%3};" \
                 : "+f"((c)[0]), "+f"((c)[1]), "+f"((c)[2]), "+f"((c)[3]) \
                 : "r"((a)[0]), "r"((a)[1]), "r"((a)[2]), "r"((a)[3]), "r"(b0), "r"(b1))

// ───────────── projections (fp32, merged enc/pred) ─────────────
__global__ __launch_bounds__(256) void proj_both_kernel(
    const float* __restrict__ encI, const float* __restrict__ WE, const float* __restrict__ bE,
    const float* __restrict__ predI, const float* __restrict__ WP, const float* __restrict__ bP,
    float* __restrict__ encO, float* __restrict__ predO)
{
    const float *A, *W, *bias; float* out; int M, K;
    if (blockIdx.z == 0) { A = encI;  W = WE; bias = bE; out = encO;  M = 1600; K = 512; }
    else                 { A = predI; W = WP; bias = bP; out = predO; M = 800;  K = 640; }
    const int N = 512;
    const int m0 = blockIdx.y * 64;
    if (m0 >= M) return;
    const int n0 = blockIdx.x * 64;

    __shared__ float As[16][68];
    __shared__ float Ws[16][68];
    const int tid = threadIdx.x;
    const int tx = tid & 15, ty = tid >> 4;
    const int lm = tid >> 2;
    const int lk = (tid & 3) << 2;
    const int arow = m0 + lm;
    const float* Ap = A + (size_t)arow * K;
    const float* Wp = W + (size_t)(n0 + lm) * K;
    float acc[4][4] = {};

    for (int k0 = 0; k0 < K; k0 += 16) {
        float4 av = make_float4(0.f, 0.f, 0.f, 0.f);
        if (arow < M) av = *(const float4*)(Ap + k0 + lk);
        float4 wv = *(const float4*)(Wp + k0 + lk);
        As[lk+0][lm] = av.x; As[lk+1][lm] = av.y; As[lk+2][lm] = av.z; As[lk+3][lm] = av.w;
        Ws[lk+0][lm] = wv.x; Ws[lk+1][lm] = wv.y; Ws[lk+2][lm] = wv.z; Ws[lk+3][lm] = wv.w;
        __syncthreads();
        #pragma unroll
        for (int kk = 0; kk < 16; kk++) {
            float a[4], w[4];
            *(float4*)a = *(const float4*)&As[kk][ty << 2];
            *(float4*)w = *(const float4*)&Ws[kk][tx << 2];
            #pragma unroll
            for (int i = 0; i < 4; i++)
                #pragma unroll
                for (int j = 0; j < 4; j++)
                    acc[i][j] = fmaf(a[i], w[j], acc[i][j]);
        }
        __syncthreads();
    }
    float4 bv = *(const float4*)(bias + n0 + (tx << 2));
    #pragma unroll
    for (int i = 0; i < 4; i++) {
        int row = m0 + (ty << 2) + i;
        if (row < M) {
            float4 v;
            v.x = acc[i][0] + bv.x; v.y = acc[i][1] + bv.y;
            v.z = acc[i][2] + bv.z; v.w = acc[i][3] + bv.w;
            *(float4*)(out + (size_t)row * N + n0 + (tx << 2)) = v;
        }
    }
}

// W_out fp32 -> fp16 (one rounding, persistent copy)
__global__ __launch_bounds__(256) void convert_w_kernel(const float* __restrict__ W,
                                                        __half* __restrict__ out)
{
    int i = (blockIdx.x * 256 + threadIdx.x) * 8;   // 65536 threads * 8 = 524288
    float4 a = *(const float4*)(W + i);
    float4 b = *(const float4*)(W + i + 4);
    uint4 o;
    o.x = pack_h2(a.x, a.y); o.y = pack_h2(a.z, a.w);
    o.z = pack_h2(b.x, b.y); o.w = pack_h2(b.z, b.w);
    *(uint4*)(out + i) = o;
}

// ───────────── fused joint GEMM: mma.sync fp16 ─────────────
// CTA 128x128, BK=32 halves (64B rows), 2-stage smem, 8 warps (4m x 2n),
// warp tile 32x64. A = relu(enc+pred) rounded to fp16 in the loader.
#define BK       32
#define NCHUNK   (H_ / BK)            // 16
#define A_SZ     (128 * BK * 2)       // 8192 B
#define B_SZ     (128 * BK * 2)       // 8192 B
#define STAGE_SZ (A_SZ + B_SZ)        // 16384 B

__global__ __launch_bounds__(256, 1) void joint_mma_kernel(
    const float* __restrict__ bout, float* __restrict__ out)
{
    __shared__ char smem[2 * STAGE_SZ];
    const uint32_t smb = smem_u32(smem);

    const int tid  = threadIdx.x;
    const int wid  = tid >> 5, lane = tid & 31;
    const int wm   = wid & 3;          // warp m block (32 rows)
    const int wn   = wid >> 2;         // warp n block (64 cols)
    const int m0   = blockIdx.y * 128;
    const int n0   = blockIdx.x * 128;

    // ── loader precompute: 2 granules (16B of halves = 8 values) per thread
    const int kseg = tid & 3;                    // 8-half segment within 32
    const float* encp[2]; const float* predp[2]; const __half* wp[2];
    uint32_t aoff[2], boff[2];
    #pragma unroll
    for (int g = 0; g < 2; g++) {
        int row = (tid + 256 * g) >> 2;          // 0..127
        int r = m0 + row;
        int bt = r / U_;
        int u  = r - bt * U_;
        int bb = bt / T_;
        encp[g]  = g_enc  + (size_t)bt * H_ + kseg * 8;
        predp[g] = g_pred + ((size_t)bb * U_ + u) * H_ + kseg * 8;
        wp[g]    = g_wout + (size_t)(n0 + row) * H_ + kseg * 8;
        uint32_t sw = (uint32_t)(kseg ^ ((row >> 1) & 3)) << 4;
        aoff[g] = (uint32_t)row * 64u + sw;              // within A region
        boff[g] = A_SZ + (uint32_t)row * 64u + sw;       // within stage
    }

    // ── ldmatrix address precompute
    uint32_t aab[2]; int akey[2];
    const int ahi = lane >> 4;                   // k-octet selector
    #pragma unroll
    for (int mt = 0; mt < 2; mt++) {
        int rA = wm * 32 + mt * 16 + (lane & 15);
        aab[mt]  = smb + (uint32_t)rA * 64u;
        akey[mt] = (rA >> 1) & 3;
    }
    uint32_t bab[4]; int bkey[4];
    const int bhi = (lane >> 3) & 1;             // k-octet selector
    #pragma unroll
    for (int p = 0; p < 4; p++) {
        int rB = wn * 64 + (2 * p + (lane >> 4)) * 8 + (lane & 7);
        bab[p]  = smb + A_SZ + (uint32_t)rB * 64u;
        bkey[p] = (rB >> 1) & 3;
    }

    float acc[2][8][4] = {};

    // ── helpers (lambdas)
    auto load_A_regs = [&](int k0, float4 e[2][2], float4 pr[2][2]) {
        #pragma unroll
        for (int g = 0; g < 2; g++) {
            e[g][0]  = *(const float4*)(encp[g]  + k0);
            e[g][1]  = *(const float4*)(encp[g]  + k0 + 4);
            pr[g][0] = *(const float4*)(predp[g] + k0);
            pr[g][1] = *(const float4*)(predp[g] + k0 + 4);
        }
    };
    auto sts_A = [&](int st, float4 e[2][2], float4 pr[2][2]) {
        #pragma unroll
        for (int g = 0; g < 2; g++) {
            uint4 o;
            o.x = pack_h2(fmaxf(e[g][0].x + pr[g][0].x, 0.f), fmaxf(e[g][0].y + pr[g][0].y, 0.f));
            o.y = pack_h2(fmaxf(e[g][0].z + pr[g][0].z, 0.f), fmaxf(e[g][0].w + pr[g][0].w, 0.f));
            o.z = pack_h2(fmaxf(e[g][1].x + pr[g][1].x, 0.f), fmaxf(e[g][1].y + pr[g][1].y, 0.f));
            o.w = pack_h2(fmaxf(e[g][1].z + pr[g][1].z, 0.f), fmaxf(e[g][1].w + pr[g][1].w, 0.f));
            *(uint4*)(smem + st * STAGE_SZ + aoff[g]) = o;
        }
    };
    auto issue_B = [&](int k0, int st) {
        #pragma unroll
        for (int g = 0; g < 2; g++)
            CP_ASYNC16(smb + st * STAGE_SZ + boff[g], wp[g] + k0);
        CP_COMMIT();
    };
    auto compute = [&](int st) {
        const uint32_t stb = (uint32_t)st * STAGE_SZ;
        #pragma unroll
        for (int ks = 0; ks < 2; ks++) {
            uint32_t a[2][4];
            #pragma unroll
            for (int mt = 0; mt < 2; mt++) {
                uint32_t ad = aab[mt] + stb + ((uint32_t)((ks * 2 + ahi) ^ akey[mt]) << 4);
                LDMATRIX_X4(a[mt][0], a[mt][1], a[mt][2], a[mt][3], ad);
            }
            uint32_t b[4][4];
            #pragma unroll
            for (int p = 0; p < 4; p++) {
                uint32_t bd = bab[p] + stb + ((uint32_t)((ks * 2 + bhi) ^ bkey[p]) << 4);
                LDMATRIX_X4(b[p][0], b[p][1], b[p][2], b[p][3], bd);
            }
            #pragma unroll
            for (int mt = 0; mt < 2; mt++)
                #pragma unroll
                for (int p = 0; p < 4; p++) {
                    MMA16816(acc[mt][2*p],   a[mt], b[p][0], b[p][1]);
                    MMA16816(acc[mt][2*p+1], a[mt], b[p][2], b[p][3]);
                }
        }
    };

    // ── prologue: stage 0
    {
        float4 e[2][2], pr[2][2];
        issue_B(0, 0);
        load_A_regs(0, e, pr);
        sts_A(0, e, pr);
        CP_WAIT0();
        __syncthreads();
    }

    // ── mainloop
    for (int c = 0; c < NCHUNK; ++c) {
        const int st = c & 1, nxt = st ^ 1;
        float4 e[2][2], pr[2][2];
        if (c + 1 < NCHUNK) {
            issue_B((c + 1) * BK, nxt);
            load_A_regs((c + 1) * BK, e, pr);
        }
        compute(st);
        if (c + 1 < NCHUNK) {
            sts_A(nxt, e, pr);
            CP_WAIT0();
        }
        __syncthreads();
    }

    // ── epilogue: direct coalesced STG (each quad row = full 32B sector)
    const int r0 = m0 + wm * 32 + (lane >> 2);
    const int c0 = n0 + wn * 64 + (lane & 3) * 2;
    float2 bb[8];
    #pragma unroll
    for (int nt = 0; nt < 8; nt++) bb[nt] = *(const float2*)(bout + c0 + nt * 8);
    #pragma unroll
    for (int mt = 0; mt < 2; mt++)
        #pragma unroll
        for (int rh = 0; rh < 2; rh++) {
            const size_t rbase = (size_t)(r0 + mt * 16 + rh * 8) * V_ + c0;
            #pragma unroll
            for (int nt = 0; nt < 8; nt++) {
                float2 v;
                v.x = (acc[mt][nt][rh * 2 + 0] + bb[nt].x) * 0.1f;
                v.y = (acc[mt][nt][rh * 2 + 1] + bb[nt].y) * 0.1f;
                *(float2*)(out + rbase + nt * 8) = v;
            }
        }
}

// ───────────── launch ─────────────
extern "C" void kernel_launch(void* const* d_in, const int* in_sizes, int n_in,
                              void* d_out, int out_size)
{
    const float* enc_in  = (const float*)d_in[0];
    const float* pred_in = (const float*)d_in[1];
    const float* W_enc   = (const float*)d_in[2];
    const float* b_enc   = (const float*)d_in[3];
    const float* W_pred  = (const float*)d_in[4];
    const float* b_pred  = (const float*)d_in[5];
    const float* W_out   = (const float*)d_in[6];
    const float* b_out   = (const float*)d_in[7];
    float* out = (float*)d_out;

    float *genc = nullptr, *gpred = nullptr;
    __half* gw = nullptr;
    cudaGetSymbolAddress((void**)&genc, g_enc);
    cudaGetSymbolAddress((void**)&gpred, g_pred);
    cudaGetSymbolAddress((void**)&gw, g_wout);

    proj_both_kernel<<<dim3(8, 25, 2), 256>>>(
        enc_in, W_enc, b_enc, pred_in, W_pred, b_pred, genc, gpred);
    convert_w_kernel<<<256, 256>>>(W_out, gw);
    // joint: M=160000 -> 1250 tiles of 128, N=1024 -> 8 tiles of 128
    joint_mma_kernel<<<dim3(8, 1250), 256>>>(b_out, out);
}

// round 5
// speedup vs baseline: 5.4529x; 1.4556x over previous
#include <cuda_runtime.h>
#include <cuda_fp16.h>
#include <cstdint>

#define B_ 8
#define T_ 200
#define U_ 100
#define H_ 512
#define V_ 1024

__device__ __half g_ench [B_ * T_ * H_];  // 1.6 MB fp16 (B*T=1600, H)
__device__ __half g_predh[B_ * U_ * H_];  // 0.8 MB fp16 (B*U=800,  H)
__device__ __half g_wout [V_ * H_];       // 1.0 MB fp16 (V=1024, H)

// ───────────── helpers ─────────────
__device__ __forceinline__ uint32_t smem_u32(const void* p) {
    uint32_t a;
    asm("{ .reg .u64 t; cvta.to.shared.u64 t, %1; cvt.u32.u64 %0, t; }" : "=r"(a) : "l"(p));
    return a;
}
__device__ __forceinline__ uint32_t pack_h2(float x, float y) {
    __half2 h = __floats2half2_rn(x, y);
    return *reinterpret_cast<uint32_t*>(&h);
}
#define CP_ASYNC16(dst, src) \
    asm volatile("cp.async.cg.shared.global [%0], [%1], 16;" :: "r"(dst), "l"(src) : "memory")
#define CP_COMMIT() asm volatile("cp.async.commit_group;" ::: "memory")
#define CP_WAIT0()  asm volatile("cp.async.wait_group 0;" ::: "memory")

#define LDMATRIX_X4(r0, r1, r2, r3, addr) \
    asm volatile("ldmatrix.sync.aligned.m8n8.x4.shared.b16 {%0,%1,%2,%3}, [%4];" \
                 : "=r"(r0), "=r"(r1), "=r"(r2), "=r"(r3) : "r"(addr))

#define MMA16816(c, a, b0, b1) \
    asm volatile("mma.sync.aligned.m16n8k16.row.col.f32.f16.f16.f32 " \
                 "{%0,%1,%2,%3}, {%4,%5,%6,%7}, {%8,%9}, {%0,%1,%2,%3};" \
                 : "+f"((c)[0]), "+f"((c)[1]), "+f"((c)[2]), "+f"((c)[3]) \
                 : "r"((a)[0]), "r"((a)[1]), "r"((a)[2]), "r"((a)[3]), "r"(b0), "r"(b1))

// ───────────── projections (fp32 math, fp16 output) ─────────────
__global__ __launch_bounds__(256) void proj_both_kernel(
    const float* __restrict__ encI, const float* __restrict__ WE, const float* __restrict__ bE,
    const float* __restrict__ predI, const float* __restrict__ WP, const float* __restrict__ bP,
    __half* __restrict__ encO, __half* __restrict__ predO)
{
    const float *A, *W, *bias; __half* out; int M, K;
    if (blockIdx.z == 0) { A = encI;  W = WE; bias = bE; out = encO;  M = 1600; K = 512; }
    else                 { A = predI; W = WP; bias = bP; out = predO; M = 800;  K = 640; }
    const int N = 512;
    const int m0 = blockIdx.y * 64;
    if (m0 >= M) return;
    const int n0 = blockIdx.x * 64;

    __shared__ float As[16][68];
    __shared__ float Ws[16][68];
    const int tid = threadIdx.x;
    const int tx = tid & 15, ty = tid >> 4;
    const int lm = tid >> 2;
    const int lk = (tid & 3) << 2;
    const int arow = m0 + lm;
    const float* Ap = A + (size_t)arow * K;
    const float* Wp = W + (size_t)(n0 + lm) * K;
    float acc[4][4] = {};

    for (int k0 = 0; k0 < K; k0 += 16) {
        float4 av = make_float4(0.f, 0.f, 0.f, 0.f);
        if (arow < M) av = *(const float4*)(Ap + k0 + lk);
        float4 wv = *(const float4*)(Wp + k0 + lk);
        As[lk+0][lm] = av.x; As[lk+1][lm] = av.y; As[lk+2][lm] = av.z; As[lk+3][lm] = av.w;
        Ws[lk+0][lm] = wv.x; Ws[lk+1][lm] = wv.y; Ws[lk+2][lm] = wv.z; Ws[lk+3][lm] = wv.w;
        __syncthreads();
        #pragma unroll
        for (int kk = 0; kk < 16; kk++) {
            float a[4], w[4];
            *(float4*)a = *(const float4*)&As[kk][ty << 2];
            *(float4*)w = *(const float4*)&Ws[kk][tx << 2];
            #pragma unroll
            for (int i = 0; i < 4; i++)
                #pragma unroll
                for (int j = 0; j < 4; j++)
                    acc[i][j] = fmaf(a[i], w[j], acc[i][j]);
        }
        __syncthreads();
    }
    float4 bv = *(const float4*)(bias + n0 + (tx << 2));
    #pragma unroll
    for (int i = 0; i < 4; i++) {
        int row = m0 + (ty << 2) + i;
        if (row < M) {
            uint2 h;
            h.x = pack_h2(acc[i][0] + bv.x, acc[i][1] + bv.y);
            h.y = pack_h2(acc[i][2] + bv.z, acc[i][3] + bv.w);
            *(uint2*)(out + (size_t)row * N + n0 + (tx << 2)) = h;
        }
    }
}

// W_out fp32 -> fp16 (one rounding, persistent copy)
__global__ __launch_bounds__(256) void convert_w_kernel(const float* __restrict__ W,
                                                        __half* __restrict__ out)
{
    int i = (blockIdx.x * 256 + threadIdx.x) * 8;
    float4 a = *(const float4*)(W + i);
    float4 b = *(const float4*)(W + i + 4);
    uint4 o;
    o.x = pack_h2(a.x, a.y); o.y = pack_h2(a.z, a.w);
    o.z = pack_h2(b.x, b.y); o.w = pack_h2(b.z, b.w);
    *(uint4*)(out + i) = o;
}

// ───────────── fused joint GEMM: mma.sync fp16, BM=256 BN=128 BK=32 ─────────
// 8 warps as 4m x 2n, warp tile 64x64, 2-stage smem (48KB exactly).
#define BK       32
#define NCHUNK   (H_ / BK)             // 16
#define A_SZ     (256 * BK * 2)        // 16384 B
#define B_SZ     (128 * BK * 2)        // 8192 B
#define STAGE_SZ (A_SZ + B_SZ)         // 24576 B

__global__ __launch_bounds__(256, 1) void joint_mma_kernel(
    const float* __restrict__ bout, float* __restrict__ out)
{
    __shared__ char smem[2 * STAGE_SZ];
    const uint32_t smb = smem_u32(smem);

    const int tid  = threadIdx.x;
    const int wid  = tid >> 5, lane = tid & 31;
    const int wm   = wid & 3;           // warp m block (64 rows)
    const int wn   = wid >> 2;          // warp n block (64 cols)
    const int m0   = blockIdx.y * 256;
    const int n0   = blockIdx.x * 128;

    // ── A loader: 256 rows x 4 segs(16B) = 1024 granules, 4/thread
    const __half* encp[4]; const __half* predp[4]; uint32_t aoff[4];
    #pragma unroll
    for (int g = 0; g < 4; g++) {
        int idx  = tid + 256 * g;
        int row  = idx >> 2;             // 0..255
        int kseg = idx & 3;
        int r  = m0 + row;
        int bt = r / U_;
        int u  = r - bt * U_;
        int bb = bt / T_;
        encp[g]  = g_ench  + (size_t)bt * H_ + kseg * 8;
        predp[g] = g_predh + ((size_t)bb * U_ + u) * H_ + kseg * 8;
        aoff[g]  = (uint32_t)row * 64u + ((uint32_t)(kseg ^ ((row >> 1) & 3)) << 4);
    }
    // ── B loader: 128 rows x 4 segs = 512 granules, 2/thread (cp.async)
    const __half* wp[2]; uint32_t boff[2];
    #pragma unroll
    for (int g = 0; g < 2; g++) {
        int idx  = tid + 256 * g;
        int row  = idx >> 2;             // 0..127
        int kseg = idx & 3;
        wp[g]   = g_wout + (size_t)(n0 + row) * H_ + kseg * 8;
        boff[g] = A_SZ + (uint32_t)row * 64u + ((uint32_t)(kseg ^ ((row >> 1) & 3)) << 4);
    }

    // ── ldmatrix address precompute
    uint32_t aab[4]; int akey[4];
    const int ahi = lane >> 4;
    #pragma unroll
    for (int mt = 0; mt < 4; mt++) {
        int rA = wm * 64 + mt * 16 + (lane & 15);
        aab[mt]  = smb + (uint32_t)rA * 64u;
        akey[mt] = (rA >> 1) & 3;
    }
    uint32_t bab[4]; int bkey[4];
    const int bhi = (lane >> 3) & 1;
    #pragma unroll
    for (int p = 0; p < 4; p++) {
        int rB = wn * 64 + (2 * p + (lane >> 4)) * 8 + (lane & 7);
        bab[p]  = smb + A_SZ + (uint32_t)rB * 64u;
        bkey[p] = (rB >> 1) & 3;
    }

    float acc[4][8][4] = {};

    auto load_A_regs = [&](int k0, uint4 e[4], uint4 pr[4]) {
        #pragma unroll
        for (int g = 0; g < 4; g++) {
            e[g]  = *(const uint4*)(encp[g]  + k0);
            pr[g] = *(const uint4*)(predp[g] + k0);
        }
    };
    auto sts_A = [&](int st, uint4 e[4], uint4 pr[4]) {
        const __half2 z = __float2half2_rn(0.f);
        #pragma unroll
        for (int g = 0; g < 4; g++) {
            uint4 o;
            const uint32_t* eu = &e[g].x;
            const uint32_t* pu = &pr[g].x;
            uint32_t* ou = &o.x;
            #pragma unroll
            for (int j = 0; j < 4; j++) {
                __half2 eh = *reinterpret_cast<const __half2*>(&eu[j]);
                __half2 ph = *reinterpret_cast<const __half2*>(&pu[j]);
                __half2 rh = __hmax2(__hadd2(eh, ph), z);
                ou[j] = *reinterpret_cast<uint32_t*>(&rh);
            }
            *(uint4*)(smem + st * STAGE_SZ + aoff[g]) = o;
        }
    };
    auto issue_B = [&](int k0, int st) {
        #pragma unroll
        for (int g = 0; g < 2; g++)
            CP_ASYNC16(smb + st * STAGE_SZ + boff[g], wp[g] + k0);
        CP_COMMIT();
    };
    auto compute = [&](int st) {
        const uint32_t stb = (uint32_t)st * STAGE_SZ;
        #pragma unroll
        for (int ks = 0; ks < 2; ks++) {
            uint32_t b[4][4];
            #pragma unroll
            for (int p = 0; p < 4; p++) {
                uint32_t bd = bab[p] + stb + ((uint32_t)((ks * 2 + bhi) ^ bkey[p]) << 4);
                LDMATRIX_X4(b[p][0], b[p][1], b[p][2], b[p][3], bd);
            }
            #pragma unroll
            for (int mt = 0; mt < 4; mt++) {
                uint32_t a[4];
                uint32_t ad = aab[mt] + stb + ((uint32_t)((ks * 2 + ahi) ^ akey[mt]) << 4);
                LDMATRIX_X4(a[0], a[1], a[2], a[3], ad);
                #pragma unroll
                for (int p = 0; p < 4; p++) {
                    MMA16816(acc[mt][2*p],   a, b[p][0], b[p][1]);
                    MMA16816(acc[mt][2*p+1], a, b[p][2], b[p][3]);
                }
            }
        }
    };

    // ── prologue: stage 0
    {
        uint4 e[4], pr[4];
        issue_B(0, 0);
        load_A_regs(0, e, pr);
        sts_A(0, e, pr);
        CP_WAIT0();
        __syncthreads();
    }

    // ── mainloop (double-buffered, software-pipelined)
    for (int c = 0; c < NCHUNK; ++c) {
        const int st = c & 1, nxt = st ^ 1;
        uint4 e[4], pr[4];
        if (c + 1 < NCHUNK) {
            issue_B((c + 1) * BK, nxt);
            load_A_regs((c + 1) * BK, e, pr);
        }
        compute(st);
        if (c + 1 < NCHUNK) {
            sts_A(nxt, e, pr);
            CP_WAIT0();
        }
        __syncthreads();
    }

    // ── epilogue: direct coalesced STG
    const int r0 = m0 + wm * 64 + (lane >> 2);
    const int c0 = n0 + wn * 64 + (lane & 3) * 2;
    float2 bb[8];
    #pragma unroll
    for (int nt = 0; nt < 8; nt++) bb[nt] = *(const float2*)(bout + c0 + nt * 8);
    #pragma unroll
    for (int mt = 0; mt < 4; mt++)
        #pragma unroll
        for (int rh = 0; rh < 2; rh++) {
            const size_t rbase = (size_t)(r0 + mt * 16 + rh * 8) * V_ + c0;
            #pragma unroll
            for (int nt = 0; nt < 8; nt++) {
                float2 v;
                v.x = (acc[mt][nt][rh * 2 + 0] + bb[nt].x) * 0.1f;
                v.y = (acc[mt][nt][rh * 2 + 1] + bb[nt].y) * 0.1f;
                *(float2*)(out + rbase + nt * 8) = v;
            }
        }
}

// ───────────── launch ─────────────
extern "C" void kernel_launch(void* const* d_in, const int* in_sizes, int n_in,
                              void* d_out, int out_size)
{
    const float* enc_in  = (const float*)d_in[0];
    const float* pred_in = (const float*)d_in[1];
    const float* W_enc   = (const float*)d_in[2];
    const float* b_enc   = (const float*)d_in[3];
    const float* W_pred  = (const float*)d_in[4];
    const float* b_pred  = (const float*)d_in[5];
    const float* W_out   = (const float*)d_in[6];
    const float* b_out   = (const float*)d_in[7];
    float* out = (float*)d_out;

    __half *genc = nullptr, *gpred = nullptr, *gw = nullptr;
    cudaGetSymbolAddress((void**)&genc, g_ench);
    cudaGetSymbolAddress((void**)&gpred, g_predh);
    cudaGetSymbolAddress((void**)&gw, g_wout);

    proj_both_kernel<<<dim3(8, 25, 2), 256>>>(
        enc_in, W_enc, b_enc, pred_in, W_pred, b_pred, genc, gpred);
    convert_w_kernel<<<256, 256>>>(W_out, gw);
    // joint: M=160000 -> 625 tiles of 256, N=1024 -> 8 tiles of 128
    joint_mma_kernel<<<dim3(8, 625), 256>>>(b_out, out);
}

// round 7
// speedup vs baseline: 6.1058x; 1.1197x over previous
#include <cuda_runtime.h>
#include <cuda_fp16.h>
#include <cstdint>

#define B_ 8
#define T_ 200
#define U_ 100
#define H_ 512
#define V_ 1024

__device__ __half g_ench [B_ * T_ * H_];  // 1.6 MB fp16
__device__ __half g_predh[B_ * U_ * H_];  // 0.8 MB fp16
__device__ __half g_wout [V_ * H_];       // 1.0 MB fp16

// ───────────── helpers ─────────────
__device__ __forceinline__ uint32_t smem_u32(const void* p) {
    uint32_t a;
    asm("{ .reg .u64 t; cvta.to.shared.u64 t, %1; cvt.u32.u64 %0, t; }" : "=r"(a) : "l"(p));
    return a;
}
__device__ __forceinline__ uint32_t pack_h2(float x, float y) {
    __half2 h = __floats2half2_rn(x, y);
    return *reinterpret_cast<uint32_t*>(&h);
}
#define CP_ASYNC16(dst, src) \
    asm volatile("cp.async.cg.shared.global [%0], [%1], 16;" :: "r"(dst), "l"(src) : "memory")
#define CP_COMMIT() asm volatile("cp.async.commit_group;" ::: "memory")
#define CP_WAIT0()  asm volatile("cp.async.wait_group 0;" ::: "memory")

#define LDMATRIX_X4(r0, r1, r2, r3, addr) \
    asm volatile("ldmatrix.sync.aligned.m8n8.x4.shared.b16 {%0,%1,%2,%3}, [%4];" \
                 : "=r"(r0), "=r"(r1), "=r"(r2), "=r"(r3) : "r"(addr))

#define MMA16816(c, a, b0, b1) \
    asm volatile("mma.sync.aligned.m16n8k16.row.col.f32.f16.f16.f32 " \
                 "{%0,%1,%2,%3}, {%4,%5,%6,%7}, {%8,%9}, {%0,%1,%2,%3};" \
                 : "+f"((c)[0]), "+f"((c)[1]), "+f"((c)[2]), "+f"((c)[3]) \
                 : "r"((a)[0]), "r"((a)[1]), "r"((a)[2]), "r"((a)[3]), "r"(b0), "r"(b1))

// ───────────── projections (fp32 math, fp16 output) ─────────────
__global__ __launch_bounds__(256) void proj_both_kernel(
    const float* __restrict__ encI, const float* __restrict__ WE, const float* __restrict__ bE,
    const float* __restrict__ predI, const float* __restrict__ WP, const float* __restrict__ bP,
    __half* __restrict__ encO, __half* __restrict__ predO)
{
    const float *A, *W, *bias; __half* out; int M, K;
    if (blockIdx.z == 0) { A = encI;  W = WE; bias = bE; out = encO;  M = 1600; K = 512; }
    else                 { A = predI; W = WP; bias = bP; out = predO; M = 800;  K = 640; }
    const int N = 512;
    const int m0 = blockIdx.y * 64;
    if (m0 >= M) return;
    const int n0 = blockIdx.x * 64;

    __shared__ float As[16][68];
    __shared__ float Ws[16][68];
    const int tid = threadIdx.x;
    const int tx = tid & 15, ty = tid >> 4;
    const int lm = tid >> 2;
    const int lk = (tid & 3) << 2;
    const int arow = m0 + lm;
    const float* Ap = A + (size_t)arow * K;
    const float* Wp = W + (size_t)(n0 + lm) * K;
    float acc[4][4] = {};

    for (int k0 = 0; k0 < K; k0 += 16) {
        float4 av = make_float4(0.f, 0.f, 0.f, 0.f);
        if (arow < M) av = *(const float4*)(Ap + k0 + lk);
        float4 wv = *(const float4*)(Wp + k0 + lk);
        As[lk+0][lm] = av.x; As[lk+1][lm] = av.y; As[lk+2][lm] = av.z; As[lk+3][lm] = av.w;
        Ws[lk+0][lm] = wv.x; Ws[lk+1][lm] = wv.y; Ws[lk+2][lm] = wv.z; Ws[lk+3][lm] = wv.w;
        __syncthreads();
        #pragma unroll
        for (int kk = 0; kk < 16; kk++) {
            float a[4], w[4];
            *(float4*)a = *(const float4*)&As[kk][ty << 2];
            *(float4*)w = *(const float4*)&Ws[kk][tx << 2];
            #pragma unroll
            for (int i = 0; i < 4; i++)
                #pragma unroll
                for (int j = 0; j < 4; j++)
                    acc[i][j] = fmaf(a[i], w[j], acc[i][j]);
        }
        __syncthreads();
    }
    float4 bv = *(const float4*)(bias + n0 + (tx << 2));
    #pragma unroll
    for (int i = 0; i < 4; i++) {
        int row = m0 + (ty << 2) + i;
        if (row < M) {
            uint2 h;
            h.x = pack_h2(acc[i][0] + bv.x, acc[i][1] + bv.y);
            h.y = pack_h2(acc[i][2] + bv.z, acc[i][3] + bv.w);
            *(uint2*)(out + (size_t)row * N + n0 + (tx << 2)) = h;
        }
    }
}

// W_out fp32 -> fp16
__global__ __launch_bounds__(256) void convert_w_kernel(const float* __restrict__ W,
                                                        __half* __restrict__ out)
{
    int i = (blockIdx.x * 256 + threadIdx.x) * 8;
    float4 a = *(const float4*)(W + i);
    float4 b = *(const float4*)(W + i + 4);
    uint4 o;
    o.x = pack_h2(a.x, a.y); o.y = pack_h2(a.z, a.w);
    o.z = pack_h2(b.x, b.y); o.w = pack_h2(b.z, b.w);
    *(uint4*)(out + i) = o;
}

// ───────────── fused joint GEMM: mma.sync fp16 ─────────────
// CTA 128x128, 128 threads (4 warps, 2m x 2n), warp tile 64x64, BK=32,
// 2-stage smem (32KB) -> 2 CTAs/SM for cross-CTA latency hiding.
#define BK       32
#define NCHUNK   (H_ / BK)             // 16
#define A_SZ     (128 * BK * 2)        // 8192 B
#define B_SZ     (128 * BK * 2)        // 8192 B
#define STAGE_SZ (A_SZ + B_SZ)         // 16384 B

__global__ __launch_bounds__(128, 2) void joint_mma_kernel(
    const float* __restrict__ bout, float* __restrict__ out)
{
    __shared__ char smem[2 * STAGE_SZ];
    const uint32_t smb = smem_u32(smem);

    const int tid  = threadIdx.x;
    const int wid  = tid >> 5, lane = tid & 31;
    const int wm   = wid & 1;           // warp m block (64 rows)
    const int wn   = wid >> 1;          // warp n block (64 cols)
    const int m0   = blockIdx.y * 128;
    const int n0   = blockIdx.x * 128;

    // ── A loader: 128 rows x 4 segs(16B) = 512 granules, 4/thread
    const __half* encp[4]; const __half* predp[4]; uint32_t aoff[4];
    #pragma unroll
    for (int g = 0; g < 4; g++) {
        int idx  = tid + 128 * g;
        int row  = idx >> 2;             // 0..127
        int kseg = idx & 3;
        int r  = m0 + row;
        int bt = r / U_;
        int u  = r - bt * U_;
        int bb = bt / T_;
        encp[g]  = g_ench  + (size_t)bt * H_ + kseg * 8;
        predp[g] = g_predh + ((size_t)bb * U_ + u) * H_ + kseg * 8;
        aoff[g]  = (uint32_t)row * 64u + ((uint32_t)(kseg ^ ((row >> 1) & 3)) << 4);
    }
    // ── B loader: 128 rows x 4 segs = 512 granules, 4/thread (cp.async)
    const __half* wp[4]; uint32_t boff[4];
    #pragma unroll
    for (int g = 0; g < 4; g++) {
        int idx  = tid + 128 * g;
        int row  = idx >> 2;
        int kseg = idx & 3;
        wp[g]   = g_wout + (size_t)(n0 + row) * H_ + kseg * 8;
        boff[g] = A_SZ + (uint32_t)row * 64u + ((uint32_t)(kseg ^ ((row >> 1) & 3)) << 4);
    }

    // ── ldmatrix address precompute
    uint32_t aab[4]; int akey[4];
    const int ahi = lane >> 4;
    #pragma unroll
    for (int mt = 0; mt < 4; mt++) {
        int rA = wm * 64 + mt * 16 + (lane & 15);
        aab[mt]  = smb + (uint32_t)rA * 64u;
        akey[mt] = (rA >> 1) & 3;
    }
    uint32_t bab[4]; int bkey[4];
    const int bhi = (lane >> 3) & 1;
    #pragma unroll
    for (int p = 0; p < 4; p++) {
        int rB = wn * 64 + (2 * p + (lane >> 4)) * 8 + (lane & 7);
        bab[p]  = smb + A_SZ + (uint32_t)rB * 64u;
        bkey[p] = (rB >> 1) & 3;
    }

    float acc[4][8][4] = {};

    auto load_A_regs = [&](int k0, uint4 e[4], uint4 pr[4]) {
        #pragma unroll
        for (int g = 0; g < 4; g++) {
            e[g]  = *(const uint4*)(encp[g]  + k0);
            pr[g] = *(const uint4*)(predp[g] + k0);
        }
    };
    auto sts_A = [&](int st, uint4 e[4], uint4 pr[4]) {
        const __half2 z = __float2half2_rn(0.f);
        #pragma unroll
        for (int g = 0; g < 4; g++) {
            uint4 o;
            const uint32_t* eu = &e[g].x;
            const uint32_t* pu = &pr[g].x;
            uint32_t* ou = &o.x;
            #pragma unroll
            for (int j = 0; j < 4; j++) {
                __half2 eh = *reinterpret_cast<const __half2*>(&eu[j]);
                __half2 ph = *reinterpret_cast<const __half2*>(&pu[j]);
                __half2 rh = __hmax2(__hadd2(eh, ph), z);
                ou[j] = *reinterpret_cast<uint32_t*>(&rh);
            }
            *(uint4*)(smem + st * STAGE_SZ + aoff[g]) = o;
        }
    };
    auto issue_B = [&](int k0, int st) {
        #pragma unroll
        for (int g = 0; g < 4; g++)
            CP_ASYNC16(smb + st * STAGE_SZ + boff[g], wp[g] + k0);
        CP_COMMIT();
    };
    auto compute = [&](int st) {
        const uint32_t stb = (uint32_t)st * STAGE_SZ;
        #pragma unroll
        for (int ks = 0; ks < 2; ks++) {
            uint32_t b[4][4];
            #pragma unroll
            for (int p = 0; p < 4; p++) {
                uint32_t bd = bab[p] + stb + ((uint32_t)((ks * 2 + bhi) ^ bkey[p]) << 4);
                LDMATRIX_X4(b[p][0], b[p][1], b[p][2], b[p][3], bd);
            }
            #pragma unroll
            for (int mt = 0; mt < 4; mt++) {
                uint32_t a[4];
                uint32_t ad = aab[mt] + stb + ((uint32_t)((ks * 2 + ahi) ^ akey[mt]) << 4);
                LDMATRIX_X4(a[0], a[1], a[2], a[3], ad);
                #pragma unroll
                for (int p = 0; p < 4; p++) {
                    MMA16816(acc[mt][2*p],   a, b[p][0], b[p][1]);
                    MMA16816(acc[mt][2*p+1], a, b[p][2], b[p][3]);
                }
            }
        }
    };

    // ── prologue: stage 0
    {
        uint4 e[4], pr[4];
        issue_B(0, 0);
        load_A_regs(0, e, pr);
        sts_A(0, e, pr);
        CP_WAIT0();
        __syncthreads();
    }

    // ── mainloop (double-buffered, software-pipelined)
    for (int c = 0; c < NCHUNK; ++c) {
        const int st = c & 1, nxt = st ^ 1;
        uint4 e[4], pr[4];
        if (c + 1 < NCHUNK) {
            issue_B((c + 1) * BK, nxt);
            load_A_regs((c + 1) * BK, e, pr);
        }
        compute(st);
        if (c + 1 < NCHUNK) {
            sts_A(nxt, e, pr);
            CP_WAIT0();
        }
        __syncthreads();
    }

    // ── epilogue: direct coalesced STG
    const int r0 = m0 + wm * 64 + (lane >> 2);
    const int c0 = n0 + wn * 64 + (lane & 3) * 2;
    float2 bb[8];
    #pragma unroll
    for (int nt = 0; nt < 8; nt++) bb[nt] = *(const float2*)(bout + c0 + nt * 8);
    #pragma unroll
    for (int mt = 0; mt < 4; mt++)
        #pragma unroll
        for (int rh = 0; rh < 2; rh++) {
            const size_t rbase = (size_t)(r0 + mt * 16 + rh * 8) * V_ + c0;
            #pragma unroll
            for (int nt = 0; nt < 8; nt++) {
                float2 v;
                v.x = (acc[mt][nt][rh * 2 + 0] + bb[nt].x) * 0.1f;
                v.y = (acc[mt][nt][rh * 2 + 1] + bb[nt].y) * 0.1f;
                *(float2*)(out + rbase + nt * 8) = v;
            }
        }
}

// ───────────── launch ─────────────
extern "C" void kernel_launch(void* const* d_in, const int* in_sizes, int n_in,
                              void* d_out, int out_size)
{
    const float* enc_in  = (const float*)d_in[0];
    const float* pred_in = (const float*)d_in[1];
    const float* W_enc   = (const float*)d_in[2];
    const float* b_enc   = (const float*)d_in[3];
    const float* W_pred  = (const float*)d_in[4];
    const float* b_pred  = (const float*)d_in[5];
    const float* W_out   = (const float*)d_in[6];
    const float* b_out   = (const float*)d_in[7];
    float* out = (float*)d_out;

    __half *genc = nullptr, *gpred = nullptr, *gw = nullptr;
    cudaGetSymbolAddress((void**)&genc, g_ench);
    cudaGetSymbolAddress((void**)&gpred, g_predh);
    cudaGetSymbolAddress((void**)&gw, g_wout);

    proj_both_kernel<<<dim3(8, 25, 2), 256>>>(
        enc_in, W_enc, b_enc, pred_in, W_pred, b_pred, genc, gpred);
    convert_w_kernel<<<256, 256>>>(W_out, gw);
    // joint: M=160000 -> 1250 tiles of 128, N=1024 -> 8 tiles of 128
    joint_mma_kernel<<<dim3(8, 1250), 128>>>(b_out, out);
}

// round 8
// speedup vs baseline: 6.6209x; 1.0844x over previous
#include <cuda_runtime.h>
#include <cuda_fp16.h>
#include <cstdint>

#define B_ 8
#define T_ 200
#define U_ 100
#define H_ 512
#define V_ 1024
#define M_TOT (B_ * T_ * U_)          // 160000

__device__ __half g_ench [B_ * T_ * H_];   // 1.6 MB fp16
__device__ __half g_predh[B_ * U_ * H_];   // 0.8 MB fp16
__device__ __half g_wout [V_ * H_];        // 1.0 MB fp16
__device__ __half g_J    [(size_t)M_TOT * H_];  // 164 MB fp16: relu(enc+pred)

// ───────────── helpers ─────────────
__device__ __forceinline__ uint32_t smem_u32(const void* p) {
    uint32_t a;
    asm("{ .reg .u64 t; cvta.to.shared.u64 t, %1; cvt.u32.u64 %0, t; }" : "=r"(a) : "l"(p));
    return a;
}
__device__ __forceinline__ uint32_t pack_h2(float x, float y) {
    __half2 h = __floats2half2_rn(x, y);
    return *reinterpret_cast<uint32_t*>(&h);
}
#define CP_ASYNC16(dst, src) \
    asm volatile("cp.async.cg.shared.global [%0], [%1], 16;" :: "r"(dst), "l"(src) : "memory")
#define CP_COMMIT() asm volatile("cp.async.commit_group;" ::: "memory")
#define CP_WAIT2()  asm volatile("cp.async.wait_group 2;" ::: "memory")

#define LDMATRIX_X4(r0, r1, r2, r3, addr) \
    asm volatile("ldmatrix.sync.aligned.m8n8.x4.shared.b16 {%0,%1,%2,%3}, [%4];" \
                 : "=r"(r0), "=r"(r1), "=r"(r2), "=r"(r3) : "r"(addr))

#define MMA16816(c, a, b0, b1) \
    asm volatile("mma.sync.aligned.m16n8k16.row.col.f32.f16.f16.f32 " \
                 "{%0,%1,%2,%3}, {%4,%5,%6,%7}, {%8,%9}, {%0,%1,%2,%3};" \
                 : "+f"((c)[0]), "+f"((c)[1]), "+f"((c)[2]), "+f"((c)[3]) \
                 : "r"((a)[0]), "r"((a)[1]), "r"((a)[2]), "r"((a)[3]), "r"(b0), "r"(b1))

// ───────────── projections (fp32 math, fp16 output) ─────────────
__global__ __launch_bounds__(256) void proj_both_kernel(
    const float* __restrict__ encI, const float* __restrict__ WE, const float* __restrict__ bE,
    const float* __restrict__ predI, const float* __restrict__ WP, const float* __restrict__ bP,
    __half* __restrict__ encO, __half* __restrict__ predO)
{
    const float *A, *W, *bias; __half* out; int M, K;
    if (blockIdx.z == 0) { A = encI;  W = WE; bias = bE; out = encO;  M = 1600; K = 512; }
    else                 { A = predI; W = WP; bias = bP; out = predO; M = 800;  K = 640; }
    const int N = 512;
    const int m0 = blockIdx.y * 64;
    if (m0 >= M) return;
    const int n0 = blockIdx.x * 64;

    __shared__ float As[16][68];
    __shared__ float Ws[16][68];
    const int tid = threadIdx.x;
    const int tx = tid & 15, ty = tid >> 4;
    const int lm = tid >> 2;
    const int lk = (tid & 3) << 2;
    const int arow = m0 + lm;
    const float* Ap = A + (size_t)arow * K;
    const float* Wp = W + (size_t)(n0 + lm) * K;
    float acc[4][4] = {};

    for (int k0 = 0; k0 < K; k0 += 16) {
        float4 av = make_float4(0.f, 0.f, 0.f, 0.f);
        if (arow < M) av = *(const float4*)(Ap + k0 + lk);
        float4 wv = *(const float4*)(Wp + k0 + lk);
        As[lk+0][lm] = av.x; As[lk+1][lm] = av.y; As[lk+2][lm] = av.z; As[lk+3][lm] = av.w;
        Ws[lk+0][lm] = wv.x; Ws[lk+1][lm] = wv.y; Ws[lk+2][lm] = wv.z; Ws[lk+3][lm] = wv.w;
        __syncthreads();
        #pragma unroll
        for (int kk = 0; kk < 16; kk++) {
            float a[4], w[4];
            *(float4*)a = *(const float4*)&As[kk][ty << 2];
            *(float4*)w = *(const float4*)&Ws[kk][tx << 2];
            #pragma unroll
            for (int i = 0; i < 4; i++)
                #pragma unroll
                for (int j = 0; j < 4; j++)
                    acc[i][j] = fmaf(a[i], w[j], acc[i][j]);
        }
        __syncthreads();
    }
    float4 bv = *(const float4*)(bias + n0 + (tx << 2));
    #pragma unroll
    for (int i = 0; i < 4; i++) {
        int row = m0 + (ty << 2) + i;
        if (row < M) {
            uint2 h;
            h.x = pack_h2(acc[i][0] + bv.x, acc[i][1] + bv.y);
            h.y = pack_h2(acc[i][2] + bv.z, acc[i][3] + bv.w);
            *(uint2*)(out + (size_t)row * N + n0 + (tx << 2)) = h;
        }
    }
}

// W_out fp32 -> fp16
__global__ __launch_bounds__(256) void convert_w_kernel(const float* __restrict__ W,
                                                        __half* __restrict__ out)
{
    int i = (blockIdx.x * 256 + threadIdx.x) * 8;
    float4 a = *(const float4*)(W + i);
    float4 b = *(const float4*)(W + i + 4);
    uint4 o;
    o.x = pack_h2(a.x, a.y); o.y = pack_h2(a.z, a.w);
    o.z = pack_h2(b.x, b.y); o.w = pack_h2(b.z, b.w);
    *(uint4*)(out + i) = o;
}

// ───────────── J = relu(enc + pred), fp16 (fused A precompute) ─────────────
// 160000 rows x 512; one 16B granule (8 halves) per thread.
__global__ __launch_bounds__(256) void joint_a_kernel()
{
    const int idx = blockIdx.x * 256 + threadIdx.x;   // 10,240,000 granules
    const int r   = idx >> 6;                         // row 0..159999
    const int seg = (idx & 63) << 3;                  // half offset 0..504
    const int bt  = r / U_;
    const int u   = r - bt * U_;
    const int bb  = bt / T_;
    uint4 e = *(const uint4*)(g_ench  + (size_t)bt * H_ + seg);
    uint4 p = *(const uint4*)(g_predh + ((size_t)bb * U_ + u) * H_ + seg);
    const __half2 z = __float2half2_rn(0.f);
    uint4 o;
    const uint32_t* eu = &e.x; const uint32_t* pu = &p.x; uint32_t* ou = &o.x;
    #pragma unroll
    for (int j = 0; j < 4; j++) {
        __half2 eh = *reinterpret_cast<const __half2*>(&eu[j]);
        __half2 ph = *reinterpret_cast<const __half2*>(&pu[j]);
        __half2 rh = __hmax2(__hadd2(eh, ph), z);
        ou[j] = *reinterpret_cast<uint32_t*>(&rh);
    }
    *(uint4*)(g_J + (size_t)r * H_ + seg) = o;
}

// ───────────── joint GEMM: pure cp.async 4-stage pipeline ─────────────
// CTA 128x128, 128 threads (4 warps, 2m x 2n), warp tile 64x64, BK=32.
// smem: 4 stages x (A 8KB + B 8KB) = 64KB dynamic -> 2 CTAs/SM.
#define BK       32
#define NCHUNK   (H_ / BK)             // 16
#define A_SZ     (128 * BK * 2)        // 8192 B
#define B_SZ     (128 * BK * 2)        // 8192 B
#define STAGE_SZ (A_SZ + B_SZ)         // 16384 B
#define STAGES   4
#define SMEM_DYN (STAGES * STAGE_SZ)   // 65536 B

__global__ __launch_bounds__(128, 2) void joint_mma_kernel(
    const float* __restrict__ bout, float* __restrict__ out)
{
    extern __shared__ char smem[];
    const uint32_t smb = smem_u32(smem);

    const int tid  = threadIdx.x;
    const int wid  = tid >> 5, lane = tid & 31;
    const int wm   = wid & 1;
    const int wn   = wid >> 1;
    const int m0   = blockIdx.y * 128;
    const int n0   = blockIdx.x * 128;

    // loaders: 128 rows x 4 segs(16B) = 512 granules each, 4/thread
    const __half* jp[4]; const __half* wp[4]; uint32_t aoff[4], boff[4];
    #pragma unroll
    for (int g = 0; g < 4; g++) {
        int idx  = tid + 128 * g;
        int row  = idx >> 2;
        int kseg = idx & 3;
        jp[g] = g_J    + (size_t)(m0 + row) * H_ + kseg * 8;
        wp[g] = g_wout + (size_t)(n0 + row) * H_ + kseg * 8;
        uint32_t sw = (uint32_t)(kseg ^ ((row >> 1) & 3)) << 4;
        aoff[g] = (uint32_t)row * 64u + sw;
        boff[g] = A_SZ + (uint32_t)row * 64u + sw;
    }

    // ldmatrix address precompute
    uint32_t aab[4]; int akey[4];
    const int ahi = lane >> 4;
    #pragma unroll
    for (int mt = 0; mt < 4; mt++) {
        int rA = wm * 64 + mt * 16 + (lane & 15);
        aab[mt]  = smb + (uint32_t)rA * 64u;
        akey[mt] = (rA >> 1) & 3;
    }
    uint32_t bab[4]; int bkey[4];
    const int bhi = (lane >> 3) & 1;
    #pragma unroll
    for (int p = 0; p < 4; p++) {
        int rB = wn * 64 + (2 * p + (lane >> 4)) * 8 + (lane & 7);
        bab[p]  = smb + A_SZ + (uint32_t)rB * 64u;
        bkey[p] = (rB >> 1) & 3;
    }

    float acc[4][8][4] = {};

    auto issue = [&](int c) {
        const uint32_t stb = smb + (uint32_t)(c & (STAGES - 1)) * STAGE_SZ;
        const int k0 = c * BK;
        #pragma unroll
        for (int g = 0; g < 4; g++) CP_ASYNC16(stb + aoff[g], jp[g] + k0);
        #pragma unroll
        for (int g = 0; g < 4; g++) CP_ASYNC16(stb + boff[g], wp[g] + k0);
        CP_COMMIT();
    };
    auto compute = [&](int st) {
        const uint32_t stb = (uint32_t)st * STAGE_SZ;
        #pragma unroll
        for (int ks = 0; ks < 2; ks++) {
            uint32_t b[4][4];
            #pragma unroll
            for (int p = 0; p < 4; p++) {
                uint32_t bd = bab[p] + stb + ((uint32_t)((ks * 2 + bhi) ^ bkey[p]) << 4);
                LDMATRIX_X4(b[p][0], b[p][1], b[p][2], b[p][3], bd);
            }
            #pragma unroll
            for (int mt = 0; mt < 4; mt++) {
                uint32_t a[4];
                uint32_t ad = aab[mt] + stb + ((uint32_t)((ks * 2 + ahi) ^ akey[mt]) << 4);
                LDMATRIX_X4(a[0], a[1], a[2], a[3], ad);
                #pragma unroll
                for (int p = 0; p < 4; p++) {
                    MMA16816(acc[mt][2*p],   a, b[p][0], b[p][1]);
                    MMA16816(acc[mt][2*p+1], a, b[p][2], b[p][3]);
                }
            }
        }
    };

    // prologue: fill 3 stages
    issue(0); issue(1); issue(2);

    // mainloop: wait -> sync -> prefetch c+3 -> compute c
    for (int c = 0; c < NCHUNK; ++c) {
        CP_WAIT2();
        __syncthreads();
        if (c + 3 < NCHUNK) issue(c + 3);
        compute(c & (STAGES - 1));
    }

    // epilogue: direct coalesced STG
    const int r0 = m0 + wm * 64 + (lane >> 2);
    const int c0 = n0 + wn * 64 + (lane & 3) * 2;
    float2 bb[8];
    #pragma unroll
    for (int nt = 0; nt < 8; nt++) bb[nt] = *(const float2*)(bout + c0 + nt * 8);
    #pragma unroll
    for (int mt = 0; mt < 4; mt++)
        #pragma unroll
        for (int rh = 0; rh < 2; rh++) {
            const size_t rbase = (size_t)(r0 + mt * 16 + rh * 8) * V_ + c0;
            #pragma unroll
            for (int nt = 0; nt < 8; nt++) {
                float2 v;
                v.x = (acc[mt][nt][rh * 2 + 0] + bb[nt].x) * 0.1f;
                v.y = (acc[mt][nt][rh * 2 + 1] + bb[nt].y) * 0.1f;
                *(float2*)(out + rbase + nt * 8) = v;
            }
        }
}

// ───────────── launch ─────────────
extern "C" void kernel_launch(void* const* d_in, const int* in_sizes, int n_in,
                              void* d_out, int out_size)
{
    const float* enc_in  = (const float*)d_in[0];
    const float* pred_in = (const float*)d_in[1];
    const float* W_enc   = (const float*)d_in[2];
    const float* b_enc   = (const float*)d_in[3];
    const float* W_pred  = (const float*)d_in[4];
    const float* b_pred  = (const float*)d_in[5];
    const float* W_out   = (const float*)d_in[6];
    const float* b_out   = (const float*)d_in[7];
    float* out = (float*)d_out;

    __half *genc = nullptr, *gpred = nullptr, *gw = nullptr;
    cudaGetSymbolAddress((void**)&genc, g_ench);
    cudaGetSymbolAddress((void**)&gpred, g_predh);
    cudaGetSymbolAddress((void**)&gw, g_wout);

    cudaFuncSetAttribute(joint_mma_kernel,
                         cudaFuncAttributeMaxDynamicSharedMemorySize, SMEM_DYN);

    proj_both_kernel<<<dim3(8, 25, 2), 256>>>(
        enc_in, W_enc, b_enc, pred_in, W_pred, b_pred, genc, gpred);
    convert_w_kernel<<<256, 256>>>(W_out, gw);
    joint_a_kernel<<<40000, 256>>>();
    // joint: M=160000 -> 1250 tiles of 128, N=1024 -> 8 tiles of 128
    joint_mma_kernel<<<dim3(8, 1250), 128, SMEM_DYN>>>(b_out, out);
}

// round 9
// speedup vs baseline: 6.9986x; 1.0570x over previous
#include <cuda_runtime.h>
#include <cuda_fp16.h>
#include <cstdint>

#define B_ 8
#define T_ 200
#define U_ 100
#define H_ 512
#define V_ 1024
#define M_TOT (B_ * T_ * U_)          // 160000

__device__ __half g_ench [B_ * T_ * H_];   // 1.6 MB fp16
__device__ __half g_predh[B_ * U_ * H_];   // 0.8 MB fp16
__device__ __half g_wout [V_ * H_];        // 1.0 MB fp16
__device__ __half g_J    [(size_t)M_TOT * H_];  // 164 MB fp16: relu(enc+pred)

// ───────────── helpers ─────────────
__device__ __forceinline__ uint32_t smem_u32(const void* p) {
    uint32_t a;
    asm("{ .reg .u64 t; cvta.to.shared.u64 t, %1; cvt.u32.u64 %0, t; }" : "=r"(a) : "l"(p));
    return a;
}
__device__ __forceinline__ uint32_t pack_h2(float x, float y) {
    __half2 h = __floats2half2_rn(x, y);
    return *reinterpret_cast<uint32_t*>(&h);
}
#define CP_ASYNC16(dst, src) \
    asm volatile("cp.async.cg.shared.global [%0], [%1], 16;" :: "r"(dst), "l"(src) : "memory")
#define CP_COMMIT() asm volatile("cp.async.commit_group;" ::: "memory")
#define CP_WAIT1()  asm volatile("cp.async.wait_group 1;" ::: "memory")

#define LDMATRIX_X4(r0, r1, r2, r3, addr) \
    asm volatile("ldmatrix.sync.aligned.m8n8.x4.shared.b16 {%0,%1,%2,%3}, [%4];" \
                 : "=r"(r0), "=r"(r1), "=r"(r2), "=r"(r3) : "r"(addr))

#define MMA16816(c, a, b0, b1) \
    asm volatile("mma.sync.aligned.m16n8k16.row.col.f32.f16.f16.f32 " \
                 "{%0,%1,%2,%3}, {%4,%5,%6,%7}, {%8,%9}, {%0,%1,%2,%3};" \
                 : "+f"((c)[0]), "+f"((c)[1]), "+f"((c)[2]), "+f"((c)[3]) \
                 : "r"((a)[0]), "r"((a)[1]), "r"((a)[2]), "r"((a)[3]), "r"(b0), "r"(b1))

// ───────────── projections (fp32 math, fp16 output) ─────────────
__global__ __launch_bounds__(256) void proj_both_kernel(
    const float* __restrict__ encI, const float* __restrict__ WE, const float* __restrict__ bE,
    const float* __restrict__ predI, const float* __restrict__ WP, const float* __restrict__ bP,
    __half* __restrict__ encO, __half* __restrict__ predO)
{
    const float *A, *W, *bias; __half* out; int M, K;
    if (blockIdx.z == 0) { A = encI;  W = WE; bias = bE; out = encO;  M = 1600; K = 512; }
    else                 { A = predI; W = WP; bias = bP; out = predO; M = 800;  K = 640; }
    const int N = 512;
    const int m0 = blockIdx.y * 64;
    if (m0 >= M) return;
    const int n0 = blockIdx.x * 64;

    __shared__ float As[16][68];
    __shared__ float Ws[16][68];
    const int tid = threadIdx.x;
    const int tx = tid & 15, ty = tid >> 4;
    const int lm = tid >> 2;
    const int lk = (tid & 3) << 2;
    const int arow = m0 + lm;
    const float* Ap = A + (size_t)arow * K;
    const float* Wp = W + (size_t)(n0 + lm) * K;
    float acc[4][4] = {};

    for (int k0 = 0; k0 < K; k0 += 16) {
        float4 av = make_float4(0.f, 0.f, 0.f, 0.f);
        if (arow < M) av = *(const float4*)(Ap + k0 + lk);
        float4 wv = *(const float4*)(Wp + k0 + lk);
        As[lk+0][lm] = av.x; As[lk+1][lm] = av.y; As[lk+2][lm] = av.z; As[lk+3][lm] = av.w;
        Ws[lk+0][lm] = wv.x; Ws[lk+1][lm] = wv.y; Ws[lk+2][lm] = wv.z; Ws[lk+3][lm] = wv.w;
        __syncthreads();
        #pragma unroll
        for (int kk = 0; kk < 16; kk++) {
            float a[4], w[4];
            *(float4*)a = *(const float4*)&As[kk][ty << 2];
            *(float4*)w = *(const float4*)&Ws[kk][tx << 2];
            #pragma unroll
            for (int i = 0; i < 4; i++)
                #pragma unroll
                for (int j = 0; j < 4; j++)
                    acc[i][j] = fmaf(a[i], w[j], acc[i][j]);
        }
        __syncthreads();
    }
    float4 bv = *(const float4*)(bias + n0 + (tx << 2));
    #pragma unroll
    for (int i = 0; i < 4; i++) {
        int row = m0 + (ty << 2) + i;
        if (row < M) {
            uint2 h;
            h.x = pack_h2(acc[i][0] + bv.x, acc[i][1] + bv.y);
            h.y = pack_h2(acc[i][2] + bv.z, acc[i][3] + bv.w);
            *(uint2*)(out + (size_t)row * N + n0 + (tx << 2)) = h;
        }
    }
}

// W_out fp32 -> fp16
__global__ __launch_bounds__(256) void convert_w_kernel(const float* __restrict__ W,
                                                        __half* __restrict__ out)
{
    int i = (blockIdx.x * 256 + threadIdx.x) * 8;
    float4 a = *(const float4*)(W + i);
    float4 b = *(const float4*)(W + i + 4);
    uint4 o;
    o.x = pack_h2(a.x, a.y); o.y = pack_h2(a.z, a.w);
    o.z = pack_h2(b.x, b.y); o.w = pack_h2(b.z, b.w);
    *(uint4*)(out + i) = o;
}

// ───────────── J = relu(enc + pred), fp16 ─────────────
__global__ __launch_bounds__(256) void joint_a_kernel()
{
    const int idx = blockIdx.x * 256 + threadIdx.x;
    const int r   = idx >> 6;
    const int seg = (idx & 63) << 3;
    const int bt  = r / U_;
    const int u   = r - bt * U_;
    const int bb  = bt / T_;
    uint4 e = *(const uint4*)(g_ench  + (size_t)bt * H_ + seg);
    uint4 p = *(const uint4*)(g_predh + ((size_t)bb * U_ + u) * H_ + seg);
    const __half2 z = __float2half2_rn(0.f);
    uint4 o;
    const uint32_t* eu = &e.x; const uint32_t* pu = &p.x; uint32_t* ou = &o.x;
    #pragma unroll
    for (int j = 0; j < 4; j++) {
        __half2 eh = *reinterpret_cast<const __half2*>(&eu[j]);
        __half2 ph = *reinterpret_cast<const __half2*>(&pu[j]);
        __half2 rh = __hmax2(__hadd2(eh, ph), z);
        ou[j] = *reinterpret_cast<uint32_t*>(&rh);
    }
    *(uint4*)(g_J + (size_t)r * H_ + seg) = o;
}

// ───────────── joint GEMM: BK=64, 3-stage ring, 1 barrier/chunk ─────────────
// CTA 128x128, 128 threads (4 warps, 2m x 2n), warp tile 64x64.
// Rows are 128B (64 halves), full SW128 swizzle: seg ^= (row & 7).
#define BK       64
#define NCHUNK   (H_ / BK)             // 8
#define A_SZ     (128 * BK * 2)        // 16384 B
#define B_SZ     (128 * BK * 2)        // 16384 B
#define STAGE_SZ (A_SZ + B_SZ)         // 32768 B
#define STAGES   3
#define SMEM_DYN (STAGES * STAGE_SZ)   // 98304 B

__global__ __launch_bounds__(128, 2) void joint_mma_kernel(
    const float* __restrict__ bout, float* __restrict__ out)
{
    extern __shared__ char smem[];
    const uint32_t smb = smem_u32(smem);

    const int tid  = threadIdx.x;
    const int wid  = tid >> 5, lane = tid & 31;
    const int wm   = wid & 1;
    const int wn   = wid >> 1;
    const int m0   = blockIdx.y * 128;
    const int n0   = blockIdx.x * 128;

    // ── loaders: 128 rows x 8 segs(16B) = 1024 granules each; 8/thread.
    //    granule g: row = (tid>>3) + 16g, kseg = tid&7  → off[g] = off0 + g*2048.
    const int lrow = tid >> 3;
    const int kseg = tid & 7;
    const __half* jp0 = g_J    + (size_t)(m0 + lrow) * H_ + kseg * 8;
    const __half* wp0 = g_wout + (size_t)(n0 + lrow) * H_ + kseg * 8;
    const uint32_t ld0 = (uint32_t)lrow * 128u + ((uint32_t)(kseg ^ (lrow & 7)) << 4);

    // ── ldmatrix bases (swizzle key is lane-only: row & 7 == lane & 7)
    const uint32_t xkey = (uint32_t)(lane & 7);
    const int ahi = lane >> 4;                 // A k-octet selector
    const int bhi = (lane >> 3) & 1;           // B k-octet selector
    const uint32_t aab0 = smb + (uint32_t)(wm * 64 + (lane & 15)) * 128u;
    const uint32_t bab0 = smb + A_SZ + (uint32_t)(wn * 64 + (lane >> 4) * 8 + (lane & 7)) * 128u;

    float acc[4][8][4] = {};

    auto issue = [&](int c) {
        const uint32_t stb = smb + (uint32_t)(c % STAGES) * STAGE_SZ;
        const int k0 = c * BK;
        const __half* j = jp0 + k0;
        const __half* w = wp0 + k0;
        #pragma unroll
        for (int g = 0; g < 8; g++)
            CP_ASYNC16(stb + ld0 + g * 2048u, j + (size_t)g * 16 * H_);
        #pragma unroll
        for (int g = 0; g < 8; g++)
            CP_ASYNC16(stb + A_SZ + ld0 + g * 2048u, w + (size_t)g * 16 * H_);
        CP_COMMIT();
    };
    auto compute = [&](int st) {
        const uint32_t stb = (uint32_t)st * STAGE_SZ;
        #pragma unroll
        for (int ks = 0; ks < 4; ks++) {
            const uint32_t segA = ((uint32_t)(ks * 2 + ahi) ^ xkey) << 4;
            const uint32_t segB = ((uint32_t)(ks * 2 + bhi) ^ xkey) << 4;
            uint32_t b[4][4];
            #pragma unroll
            for (int p = 0; p < 4; p++)
                LDMATRIX_X4(b[p][0], b[p][1], b[p][2], b[p][3],
                            bab0 + stb + p * 2048u + segB);
            #pragma unroll
            for (int mt = 0; mt < 4; mt++) {
                uint32_t a[4];
                LDMATRIX_X4(a[0], a[1], a[2], a[3],
                            aab0 + stb + mt * 2048u + segA);
                #pragma unroll
                for (int p = 0; p < 4; p++) {
                    MMA16816(acc[mt][2*p],   a, b[p][0], b[p][1]);
                    MMA16816(acc[mt][2*p+1], a, b[p][2], b[p][3]);
                }
            }
        }
    };

    // ── prologue: 2 chunks in flight
    issue(0); issue(1);

    // ── mainloop: wait(c) → barrier → issue(c+2) → compute(c)
    //    barrier also proves compute(c-1) done CTA-wide, so stage (c+2)%3
    //    (== (c-1)%3) is free to overwrite.
    for (int c = 0; c < NCHUNK; ++c) {
        CP_WAIT1();
        __syncthreads();
        if (c + 2 < NCHUNK) issue(c + 2);
        compute(c % STAGES);
    }

    // ── epilogue: direct coalesced STG
    const int r0 = m0 + wm * 64 + (lane >> 2);
    const int c0 = n0 + wn * 64 + (lane & 3) * 2;
    float2 bb[8];
    #pragma unroll
    for (int nt = 0; nt < 8; nt++) bb[nt] = *(const float2*)(bout + c0 + nt * 8);
    #pragma unroll
    for (int mt = 0; mt < 4; mt++)
        #pragma unroll
        for (int rh = 0; rh < 2; rh++) {
            const size_t rbase = (size_t)(r0 + mt * 16 + rh * 8) * V_ + c0;
            #pragma unroll
            for (int nt = 0; nt < 8; nt++) {
                float2 v;
                v.x = (acc[mt][nt][rh * 2 + 0] + bb[nt].x) * 0.1f;
                v.y = (acc[mt][nt][rh * 2 + 1] + bb[nt].y) * 0.1f;
                *(float2*)(out + rbase + nt * 8) = v;
            }
        }
}

// ───────────── launch ─────────────
extern "C" void kernel_launch(void* const* d_in, const int* in_sizes, int n_in,
                              void* d_out, int out_size)
{
    const float* enc_in  = (const float*)d_in[0];
    const float* pred_in = (const float*)d_in[1];
    const float* W_enc   = (const float*)d_in[2];
    const float* b_enc   = (const float*)d_in[3];
    const float* W_pred  = (const float*)d_in[4];
    const float* b_pred  = (const float*)d_in[5];
    const float* W_out   = (const float*)d_in[6];
    const float* b_out   = (const float*)d_in[7];
    float* out = (float*)d_out;

    __half *genc = nullptr, *gpred = nullptr, *gw = nullptr;
    cudaGetSymbolAddress((void**)&genc, g_ench);
    cudaGetSymbolAddress((void**)&gpred, g_predh);
    cudaGetSymbolAddress((void**)&gw, g_wout);

    cudaFuncSetAttribute(joint_mma_kernel,
                         cudaFuncAttributeMaxDynamicSharedMemorySize, SMEM_DYN);

    proj_both_kernel<<<dim3(8, 25, 2), 256>>>(
        enc_in, W_enc, b_enc, pred_in, W_pred, b_pred, genc, gpred);
    convert_w_kernel<<<256, 256>>>(W_out, gw);
    joint_a_kernel<<<40000, 256>>>();
    // joint: M=160000 -> 1250 tiles of 128, N=1024 -> 8 tiles of 128
    joint_mma_kernel<<<dim3(8, 1250), 128, SMEM_DYN>>>(b_out, out);
}